// round 6
// baseline (speedup 1.0000x reference)
#include <cuda_runtime.h>
#include <math.h>

#define NBATCH 16
#define IH 512
#define IW 512
#define CH2 256
#define CW2 256
#define PLANE_Y (NBATCH * IH * IW)
#define PLANE_C (NBATCH * CH2 * CW2)

// ---- scratch planes (static device globals; no runtime allocation) ----
__device__ float g_Y[PLANE_Y];
__device__ float g_U[PLANE_C];
__device__ float g_V[PLANE_C];
__device__ float g_rY[PLANE_Y];
__device__ float g_rU[PLANE_C];
__device__ float g_rV[PLANE_C];

// ---- compile-time DCT tables, replicating numpy fp64->fp32 exactly ----
constexpr double kCos[9] = {
    1.0,
    0.98078528040323044913,
    0.92387953251128675613,
    0.83146961230254523708,
    0.70710678118654752440,
    0.55557023301960222474,
    0.38268343236508977173,
    0.19509032201612826785,
    0.0
};

__host__ __device__ constexpr double cos16(int k) {
    k &= 31;
    if (k > 16) k = 32 - k;
    return (k <= 8) ? kCos[k] : -kCos[16 - k];
}
__host__ __device__ constexpr float Dc(int i, int j) {
    return (float)((j == 0) ? 0.35355339059327376220
                            : 0.5 * cos16((2 * i + 1) * j));
}

struct WTab { float w[64][64]; };
__host__ __device__ constexpr WTab makeW() {
    WTab t{};
    for (int p = 0; p < 64; p++)
        for (int f = 0; f < 64; f++)
            t.w[p][f] = Dc(p >> 3, f >> 3) * Dc(p & 7, f & 7);  // fp32 product (jnp.kron)
    return t;
}
__device__ constexpr WTab WT = makeW();

struct DTab { float d[8][8]; };
__host__ __device__ constexpr DTab makeD() {
    DTab t{};
    for (int i = 0; i < 8; i++)
        for (int j = 0; j < 8; j++)
            t.d[i][j] = Dc(i, j);
    return t;
}
__device__ constexpr DTab DT = makeD();

// ---- RGB -> YUV (+128 chroma) and 2x2 chroma mean ----
// Dot with NO fma contraction (validated bit-exact via qY == 0).
// PROBE this round: mean association P = (u0+u1)+(u2+u3).
__global__ void k_csc(const float* __restrict__ img)
{
    int t = blockIdx.x * blockDim.x + threadIdx.x;
    if (t >= PLANE_C) return;
    int cx = t & 255;
    int cy = (t >> 8) & 255;
    int b  = t >> 16;
    const float* Rp = img + (size_t)b * 3 * IH * IW;
    const float* Gp = Rp + IH * IW;
    const float* Bp = Rp + 2 * IH * IW;
    int o0 = (cy * 2) * IW + cx * 2;
    int o1 = o0 + IW;
    float2 r0 = *(const float2*)(Rp + o0), r1 = *(const float2*)(Rp + o1);
    float2 g0 = *(const float2*)(Gp + o0), g1 = *(const float2*)(Gp + o1);
    float2 b0 = *(const float2*)(Bp + o0), b1 = *(const float2*)(Bp + o1);

    float rr[4] = {r0.x, r0.y, r1.x, r1.y};
    float gg[4] = {g0.x, g0.y, g1.x, g1.y};
    float bb[4] = {b0.x, b0.y, b1.x, b1.y};
    float y[4], u[4], v[4];
#pragma unroll
    for (int i = 0; i < 4; i++) {
        float r  = __fmul_rn(rr[i], 255.0f);
        float g  = __fmul_rn(gg[i], 255.0f);
        float bl = __fmul_rn(bb[i], 255.0f);
        y[i] = __fadd_rn(__fadd_rn(__fmul_rn(r, 0.299f),
                                   __fmul_rn(g, 0.587f)),
                         __fmul_rn(bl, 0.114f));
        u[i] = __fadd_rn(__fadd_rn(__fadd_rn(__fmul_rn(r, -0.168736f),
                                             __fmul_rn(g, -0.331264f)),
                                   __fmul_rn(bl, 0.5f)), 128.0f);
        v[i] = __fadd_rn(__fadd_rn(__fadd_rn(__fmul_rn(r, 0.5f),
                                             __fmul_rn(g, -0.418688f)),
                                   __fmul_rn(bl, -0.081312f)), 128.0f);
    }
    float* yb = g_Y + (size_t)b * IH * IW;
    *(float2*)(yb + o0) = make_float2(y[0], y[1]);
    *(float2*)(yb + o1) = make_float2(y[2], y[3]);
    // PROBE P: pairwise (row sums, then add), then *0.25 (exact)
    g_U[t] = __fmul_rn(__fadd_rn(__fadd_rn(u[0], u[1]), __fadd_rn(u[2], u[3])), 0.25f);
    g_V[t] = __fmul_rn(__fadd_rn(__fadd_rn(v[0], v[1]), __fadd_rn(v[2], v[3])), 0.25f);
}

// ---- forward: 64-term sequential-FMA dot against kron(D,D), IEEE div, rint ----
// (validated bit-exact on qY)
__global__ void __launch_bounds__(128) k_fwd(int which,
                                             const float* __restrict__ qt,
                                             float* __restrict__ qout)
{
    __shared__ float Qs[64];
    if (threadIdx.x < 64) Qs[threadIdx.x] = qt[threadIdx.x];
    __syncthreads();

    int t = blockIdx.x * blockDim.x + threadIdx.x;
    const float* plane; int width, height;
    if (which == 0)      { plane = g_Y; width = IW;  height = IH;  }
    else if (which == 1) { plane = g_U; width = CW2; height = CH2; }
    else                 { plane = g_V; width = CW2; height = CH2; }
    int nbx  = width >> 3;
    int nbpi = (height >> 3) * nbx;
    if (t >= NBATCH * nbpi) return;
    int b  = t / nbpi, r = t - b * nbpi;
    int by = r / nbx,  bx = r - by * nbx;
    size_t po = ((size_t)b * height + by * 8) * width + bx * 8;
    const float* p = plane + po;

    float x[64];
#pragma unroll
    for (int i = 0; i < 8; i++) {
        float4 v0 = *(const float4*)(p + i * width);
        float4 v1 = *(const float4*)(p + i * width + 4);
        x[i*8+0] = v0.x - 128.f; x[i*8+1] = v0.y - 128.f;
        x[i*8+2] = v0.z - 128.f; x[i*8+3] = v0.w - 128.f;
        x[i*8+4] = v1.x - 128.f; x[i*8+5] = v1.y - 128.f;
        x[i*8+6] = v1.z - 128.f; x[i*8+7] = v1.w - 128.f;
    }

    float* qo = qout + (size_t)t * 64;
#pragma unroll
    for (int f0 = 0; f0 < 64; f0 += 8) {
        float a[8] = {0.f, 0.f, 0.f, 0.f, 0.f, 0.f, 0.f, 0.f};
#pragma unroll
        for (int pp = 0; pp < 64; pp++)
#pragma unroll
            for (int u = 0; u < 8; u++)
                a[u] = fmaf(x[pp], WT.w[pp][f0 + u], a[u]);
        float q[8];
#pragma unroll
        for (int u = 0; u < 8; u++)
            q[u] = rintf(__fdiv_rn(a[u], Qs[f0 + u]));
        *(float4*)(qo + f0)     = make_float4(q[0], q[1], q[2], q[3]);
        *(float4*)(qo + f0 + 4) = make_float4(q[4], q[5], q[6], q[7]);
    }
}

// ---- inverse: dequant + separable IDCT (+128) -> rec planes ----
__global__ void __launch_bounds__(128) k_inv(int which, const float* __restrict__ qt,
                                             const float* __restrict__ qin)
{
    __shared__ float Qs[64];
    if (threadIdx.x < 64) Qs[threadIdx.x] = qt[threadIdx.x];
    __syncthreads();

    int t = blockIdx.x * blockDim.x + threadIdx.x;
    float* rec; int width, height;
    if (which == 0)      { rec = g_rY; width = IW;  height = IH;  }
    else if (which == 1) { rec = g_rU; width = CW2; height = CH2; }
    else                 { rec = g_rV; width = CW2; height = CH2; }
    int nbx  = width >> 3;
    int nbpi = (height >> 3) * nbx;
    if (t >= NBATCH * nbpi) return;
    int b  = t / nbpi, r = t - b * nbpi;
    int by = r / nbx,  bx = r - by * nbx;
    size_t po = ((size_t)b * height + by * 8) * width + bx * 8;
    float* rp = rec + po;

    const float* qi = qin + (size_t)t * 64;
    float C[64];
#pragma unroll
    for (int i = 0; i < 16; i++) {
        float4 v = *(const float4*)(qi + i * 4);
        C[i*4+0] = __fmul_rn(v.x, Qs[i*4+0]);
        C[i*4+1] = __fmul_rn(v.y, Qs[i*4+1]);
        C[i*4+2] = __fmul_rn(v.z, Qs[i*4+2]);
        C[i*4+3] = __fmul_rn(v.w, Qs[i*4+3]);
    }
    float T[64];
#pragma unroll
    for (int rr = 0; rr < 8; rr++) {
#pragma unroll
        for (int j2 = 0; j2 < 8; j2++) {
            float s = 0.f;
#pragma unroll
            for (int j1 = 0; j1 < 8; j1++) s = fmaf(DT.d[rr][j1], C[j1*8 + j2], s);
            T[rr*8 + j2] = s;
        }
    }
#pragma unroll
    for (int rr = 0; rr < 8; rr++) {
        float o[8];
#pragma unroll
        for (int c = 0; c < 8; c++) {
            float s = 0.f;
#pragma unroll
            for (int j2 = 0; j2 < 8; j2++) s = fmaf(T[rr*8 + j2], DT.d[c][j2], s);
            o[c] = s + 128.f;
        }
        *(float4*)(rp + rr * width)     = make_float4(o[0], o[1], o[2], o[3]);
        *(float4*)(rp + rr * width + 4) = make_float4(o[4], o[5], o[6], o[7]);
    }
}

// ---- two-pass bilinear chroma upsample + no-fma YUV->RGB + clip + /255 ----
__device__ __forceinline__ float up2(const float* P, int y, int x)
{
    int hy = y >> 1, hx = x >> 1;
    bool sy = (y == 0) | (y == IH - 1);
    bool sx = (x == 0) | (x == IW - 1);
    int y0, y1; float wy0, wy1;
    if (y & 1) { y0 = hy;     y1 = hy + 1; wy0 = 0.75f; wy1 = 0.25f; }
    else       { y0 = hy - 1; y1 = hy;     wy0 = 0.25f; wy1 = 0.75f; }
    int x0, x1; float wx0, wx1;
    if (x & 1) { x0 = hx;     x1 = hx + 1; wx0 = 0.75f; wx1 = 0.25f; }
    else       { x0 = hx - 1; x1 = hx;     wx0 = 0.25f; wx1 = 0.75f; }
    if (sy) { y0 = hy; y1 = hy; }
    if (sx) { x0 = hx; x1 = hx; }
    float c0, c1;
    if (sy) {
        c0 = P[y0 * CW2 + x0];
        c1 = P[y0 * CW2 + x1];
    } else {
        c0 = __fadd_rn(__fmul_rn(P[y0 * CW2 + x0], wy0), __fmul_rn(P[y1 * CW2 + x0], wy1));
        c1 = __fadd_rn(__fmul_rn(P[y0 * CW2 + x1], wy0), __fmul_rn(P[y1 * CW2 + x1], wy1));
    }
    if (sx) return c0;
    return __fadd_rn(__fmul_rn(c0, wx0), __fmul_rn(c1, wx1));
}

__global__ void k_recon(float* __restrict__ out)
{
    int t = blockIdx.x * blockDim.x + threadIdx.x;
    if (t >= PLANE_Y) return;
    int x = t & 511;
    int y = (t >> 9) & 511;
    int b = t >> 18;
    float yv = g_rY[t];

    size_t cb = (size_t)b * CH2 * CW2;
    float u = __fadd_rn(up2(g_rU + cb, y, x), -128.0f);
    float v = __fadd_rn(up2(g_rV + cb, y, x), -128.0f);

    float R  = __fadd_rn(yv, __fmul_rn(v, 1.402f));
    float G  = __fadd_rn(__fadd_rn(yv, __fmul_rn(u, -0.344136f)), __fmul_rn(v, -0.714136f));
    float Bc = __fadd_rn(yv, __fmul_rn(u, 1.772f));
    R  = __fdiv_rn(fminf(fmaxf(R,  0.f), 255.f), 255.0f);
    G  = __fdiv_rn(fminf(fmaxf(G,  0.f), 255.f), 255.0f);
    Bc = __fdiv_rn(fminf(fmaxf(Bc, 0.f), 255.f), 255.0f);

    size_t ob = (size_t)b * 3 * IH * IW + (size_t)y * IW + x;
    out[ob]               = R;
    out[ob + IH * IW]     = G;
    out[ob + 2 * IH * IW] = Bc;
}

extern "C" void kernel_launch(void* const* d_in, const int* in_sizes, int n_in,
                              void* d_out, int out_size)
{
    const float* img = (const float*)d_in[0];
    const float* lq  = (const float*)d_in[1];
    const float* cq  = (const float*)d_in[2];
    float* out = (float*)d_out;

    // output layout: rgb | qY | qU | qV (reference return order, flattened)
    float* qY = out + 12582912;
    float* qU = out + 16777216;
    float* qV = out + 17825792;

    k_csc<<<(PLANE_C + 255) / 256, 256>>>(img);
    k_fwd<<<(NBATCH * 64 * 64 + 127) / 128, 128>>>(0, lq, qY);
    k_fwd<<<(NBATCH * 32 * 32 + 127) / 128, 128>>>(1, cq, qU);
    k_fwd<<<(NBATCH * 32 * 32 + 127) / 128, 128>>>(2, cq, qV);
    k_inv<<<(NBATCH * 64 * 64 + 127) / 128, 128>>>(0, lq, qY);
    k_inv<<<(NBATCH * 32 * 32 + 127) / 128, 128>>>(1, cq, qU);
    k_inv<<<(NBATCH * 32 * 32 + 127) / 128, 128>>>(2, cq, qV);
    k_recon<<<(PLANE_Y + 255) / 256, 256>>>(out);
}

// round 8
// speedup vs baseline: 1.0642x; 1.0642x over previous
#include <cuda_runtime.h>
#include <math.h>

#define NBATCH 16
#define IH 512
#define IW 512
#define CH2 256
#define CW2 256
#define PLANE_Y (NBATCH * IH * IW)
#define PLANE_C (NBATCH * CH2 * CW2)

#define NT_Y (NBATCH * 64 * 64)   // 65536 luma tiles
#define NT_C (NBATCH * 32 * 32)   // 16384 chroma tiles per plane
#define NT_ALL (NT_Y + 2 * NT_C)  // 98304

// ---- scratch planes (static device globals; no runtime allocation) ----
__device__ float g_Y[PLANE_Y];
__device__ float g_U[PLANE_C];
__device__ float g_V[PLANE_C];
__device__ float g_rY[PLANE_Y];
__device__ float g_rU[PLANE_C];
__device__ float g_rV[PLANE_C];

// ---- compile-time DCT tables, replicating numpy fp64->fp32 exactly ----
// (function, not array: usable in BOTH host constexpr context and device code)
__host__ __device__ constexpr double kCosV(int k) {
    return (k == 0) ? 1.0
         : (k == 1) ? 0.98078528040323044913
         : (k == 2) ? 0.92387953251128675613
         : (k == 3) ? 0.83146961230254523708
         : (k == 4) ? 0.70710678118654752440
         : (k == 5) ? 0.55557023301960222474
         : (k == 6) ? 0.38268343236508977173
         : (k == 7) ? 0.19509032201612826785
         : 0.0;
}

__host__ __device__ constexpr double cos16(int k) {
    k &= 31;
    if (k > 16) k = 32 - k;
    return (k <= 8) ? kCosV(k) : -kCosV(16 - k);
}
__host__ __device__ constexpr float Dc(int i, int j) {
    return (float)((j == 0) ? 0.35355339059327376220
                            : 0.5 * cos16((2 * i + 1) * j));
}

struct WTab { float w[64][64]; };
__host__ __device__ constexpr WTab makeW() {
    WTab t{};
    for (int p = 0; p < 64; p++)
        for (int f = 0; f < 64; f++)
            t.w[p][f] = Dc(p >> 3, f >> 3) * Dc(p & 7, f & 7);  // fp32 product (jnp.kron)
    return t;
}
__device__ constexpr WTab WT = makeW();

// ---- tile geometry helper (unified Y/U/V tile index) ----
struct TileInfo {
    const float* plane;   // source plane (fwd)
    float*       rec;     // dest plane (inv)
    float*       qbase;   // q output/input base
    int          width;
    int          qsel;    // 0 = luma table, 1 = chroma table
    size_t       po;      // pixel offset of tile origin in plane
    int          tp;      // tile index within plane
};

__device__ __forceinline__ TileInfo tile_info(int tile, float* qY, float* qU, float* qV)
{
    TileInfo ti;
    int tp, nbx, height;
    if (tile < NT_Y) {
        tp = tile;           ti.plane = g_Y; ti.rec = g_rY; ti.qbase = qY;
        ti.width = IW;  height = IH;  ti.qsel = 0;
    } else if (tile < NT_Y + NT_C) {
        tp = tile - NT_Y;    ti.plane = g_U; ti.rec = g_rU; ti.qbase = qU;
        ti.width = CW2; height = CH2; ti.qsel = 1;
    } else {
        tp = tile - NT_Y - NT_C; ti.plane = g_V; ti.rec = g_rV; ti.qbase = qV;
        ti.width = CW2; height = CH2; ti.qsel = 1;
    }
    nbx = ti.width >> 3;
    int nbpi = (height >> 3) * nbx;
    int b  = tp / nbpi, r = tp - b * nbpi;
    int by = r / nbx,  bx = r - by * nbx;
    ti.po = ((size_t)b * height + by * 8) * ti.width + bx * 8;
    ti.tp = tp;
    return ti;
}

// ---- RGB -> YUV (+128 chroma) and 2x2 chroma mean ----
// Reference semantics (validated bit-exact): no-FMA dot, pairwise mean.
__global__ void k_csc(const float* __restrict__ img)
{
    int t = blockIdx.x * blockDim.x + threadIdx.x;
    if (t >= PLANE_C) return;
    int cx = t & 255;
    int cy = (t >> 8) & 255;
    int b  = t >> 16;
    const float* Rp = img + (size_t)b * 3 * IH * IW;
    const float* Gp = Rp + IH * IW;
    const float* Bp = Rp + 2 * IH * IW;
    int o0 = (cy * 2) * IW + cx * 2;
    int o1 = o0 + IW;
    float2 r0 = *(const float2*)(Rp + o0), r1 = *(const float2*)(Rp + o1);
    float2 g0 = *(const float2*)(Gp + o0), g1 = *(const float2*)(Gp + o1);
    float2 b0 = *(const float2*)(Bp + o0), b1 = *(const float2*)(Bp + o1);

    float rr[4] = {r0.x, r0.y, r1.x, r1.y};
    float gg[4] = {g0.x, g0.y, g1.x, g1.y};
    float bb[4] = {b0.x, b0.y, b1.x, b1.y};
    float y[4], u[4], v[4];
#pragma unroll
    for (int i = 0; i < 4; i++) {
        float r  = __fmul_rn(rr[i], 255.0f);
        float g  = __fmul_rn(gg[i], 255.0f);
        float bl = __fmul_rn(bb[i], 255.0f);
        y[i] = __fadd_rn(__fadd_rn(__fmul_rn(r, 0.299f),
                                   __fmul_rn(g, 0.587f)),
                         __fmul_rn(bl, 0.114f));
        u[i] = __fadd_rn(__fadd_rn(__fadd_rn(__fmul_rn(r, -0.168736f),
                                             __fmul_rn(g, -0.331264f)),
                                   __fmul_rn(bl, 0.5f)), 128.0f);
        v[i] = __fadd_rn(__fadd_rn(__fadd_rn(__fmul_rn(r, 0.5f),
                                             __fmul_rn(g, -0.418688f)),
                                   __fmul_rn(bl, -0.081312f)), 128.0f);
    }
    float* yb = g_Y + (size_t)b * IH * IW;
    *(float2*)(yb + o0) = make_float2(y[0], y[1]);
    *(float2*)(yb + o1) = make_float2(y[2], y[3]);
    g_U[t] = __fmul_rn(__fadd_rn(__fadd_rn(u[0], u[1]), __fadd_rn(u[2], u[3])), 0.25f);
    g_V[t] = __fmul_rn(__fadd_rn(__fadd_rn(v[0], v[1]), __fadd_rn(v[2], v[3])), 0.25f);
}

// ---- forward accumulation for f-group FG: all weights are literal immediates ----
template<int FG>
__device__ __forceinline__ void fwd_accum(const float* __restrict__ xs, float a[8])
{
#pragma unroll
    for (int pp = 0; pp < 64; pp++) {
        float xv = xs[pp];
#pragma unroll
        for (int u = 0; u < 8; u++)
            a[u] = fmaf(xv, WT.w[pp][FG * 8 + u], a[u]);
    }
}

// ---- fused forward: all planes, 8 threads/tile via warp-specialized f-groups ----
// Block: 256 threads = 32 tiles. Warp w computes f in [8w, 8w+8) for lane-th tile.
__global__ void __launch_bounds__(256) k_fwd(const float* __restrict__ lq,
                                             const float* __restrict__ cq,
                                             float* __restrict__ qY,
                                             float* __restrict__ qU,
                                             float* __restrict__ qV)
{
    __shared__ float xs[32 * 65];   // stride 65 -> conflict-free lane access
    __shared__ float Qs[2][64];

    int t = threadIdx.x;
    if (t < 64)              Qs[0][t]      = lq[t];
    else if (t < 128)        Qs[1][t - 64] = cq[t - 64];

    // load phase: thread (tileL = t&31, row = t>>5) loads one 8-px row
    {
        int tileL = t & 31;
        int row   = t >> 5;
        int tile  = blockIdx.x * 32 + tileL;
        TileInfo ti = tile_info(tile, qY, qU, qV);
        const float* p = ti.plane + ti.po + (size_t)row * ti.width;
        float4 v0 = *(const float4*)(p);
        float4 v1 = *(const float4*)(p + 4);
        float* xr = xs + tileL * 65 + row * 8;
        xr[0] = v0.x - 128.f; xr[1] = v0.y - 128.f; xr[2] = v0.z - 128.f; xr[3] = v0.w - 128.f;
        xr[4] = v1.x - 128.f; xr[5] = v1.y - 128.f; xr[6] = v1.z - 128.f; xr[7] = v1.w - 128.f;
    }
    __syncthreads();

    // compute phase: warp-uniform f-group, lane-th tile
    int wid  = t >> 5;
    int lane = t & 31;
    int tile = blockIdx.x * 32 + lane;
    TileInfo ti = tile_info(tile, qY, qU, qV);

    float a[8] = {0.f, 0.f, 0.f, 0.f, 0.f, 0.f, 0.f, 0.f};
    const float* xl = xs + lane * 65;
    switch (wid) {
        case 0: fwd_accum<0>(xl, a); break;
        case 1: fwd_accum<1>(xl, a); break;
        case 2: fwd_accum<2>(xl, a); break;
        case 3: fwd_accum<3>(xl, a); break;
        case 4: fwd_accum<4>(xl, a); break;
        case 5: fwd_accum<5>(xl, a); break;
        case 6: fwd_accum<6>(xl, a); break;
        case 7: fwd_accum<7>(xl, a); break;
    }

    float q[8];
    const float* Qt = Qs[ti.qsel] + wid * 8;
#pragma unroll
    for (int u = 0; u < 8; u++)
        q[u] = rintf(__fdiv_rn(a[u], Qt[u]));

    float* qo = ti.qbase + (size_t)ti.tp * 64 + wid * 8;
    *(float4*)(qo)     = make_float4(q[0], q[1], q[2], q[3]);
    *(float4*)(qo + 4) = make_float4(q[4], q[5], q[6], q[7]);
}

// ---- inverse rows for output row R: D constants fold to literal immediates ----
template<int R>
__device__ __forceinline__ void inv_rows(const float* __restrict__ Cs, float o[8])
{
    float T[8];
#pragma unroll
    for (int j2 = 0; j2 < 8; j2++) {
        float s = 0.f;
#pragma unroll
        for (int j1 = 0; j1 < 8; j1++)
            s = fmaf(Dc(R, j1), Cs[j1 * 8 + j2], s);
        T[j2] = s;
    }
#pragma unroll
    for (int c = 0; c < 8; c++) {
        float s = 0.f;
#pragma unroll
        for (int j2 = 0; j2 < 8; j2++)
            s = fmaf(T[j2], Dc(c, j2), s);
        o[c] = s + 128.f;
    }
}

// ---- fused inverse: all planes, 8 threads/tile ----
__global__ void __launch_bounds__(256) k_inv(const float* __restrict__ lq,
                                             const float* __restrict__ cq,
                                             float* __restrict__ qY,
                                             float* __restrict__ qU,
                                             float* __restrict__ qV)
{
    __shared__ float Cs[32 * 65];
    __shared__ float Qs[2][64];

    int t = threadIdx.x;
    if (t < 64)              Qs[0][t]      = lq[t];
    else if (t < 128)        Qs[1][t - 64] = cq[t - 64];
    __syncthreads();

    int tileL = t & 31;
    int row   = t >> 5;
    int tile  = blockIdx.x * 32 + tileL;
    TileInfo ti = tile_info(tile, qY, qU, qV);

    // dequant row -> smem
    {
        const float* qi = ti.qbase + (size_t)ti.tp * 64 + row * 8;
        float4 v0 = *(const float4*)(qi);
        float4 v1 = *(const float4*)(qi + 4);
        const float* Qt = Qs[ti.qsel] + row * 8;
        float* cr = Cs + tileL * 65 + row * 8;
        cr[0] = __fmul_rn(v0.x, Qt[0]); cr[1] = __fmul_rn(v0.y, Qt[1]);
        cr[2] = __fmul_rn(v0.z, Qt[2]); cr[3] = __fmul_rn(v0.w, Qt[3]);
        cr[4] = __fmul_rn(v1.x, Qt[4]); cr[5] = __fmul_rn(v1.y, Qt[5]);
        cr[6] = __fmul_rn(v1.z, Qt[6]); cr[7] = __fmul_rn(v1.w, Qt[7]);
    }
    __syncthreads();

    float o[8];
    const float* cl = Cs + tileL * 65;
    switch (row) {
        case 0: inv_rows<0>(cl, o); break;
        case 1: inv_rows<1>(cl, o); break;
        case 2: inv_rows<2>(cl, o); break;
        case 3: inv_rows<3>(cl, o); break;
        case 4: inv_rows<4>(cl, o); break;
        case 5: inv_rows<5>(cl, o); break;
        case 6: inv_rows<6>(cl, o); break;
        case 7: inv_rows<7>(cl, o); break;
    }

    float* rp = ti.rec + ti.po + (size_t)row * ti.width;
    *(float4*)(rp)     = make_float4(o[0], o[1], o[2], o[3]);
    *(float4*)(rp + 4) = make_float4(o[4], o[5], o[6], o[7]);
}

// ---- two-pass bilinear chroma upsample + no-fma YUV->RGB + clip + /255 ----
__device__ __forceinline__ float up2(const float* P, int y, int x)
{
    int hy = y >> 1, hx = x >> 1;
    bool sy = (y == 0) | (y == IH - 1);
    bool sx = (x == 0) | (x == IW - 1);
    int y0, y1; float wy0, wy1;
    if (y & 1) { y0 = hy;     y1 = hy + 1; wy0 = 0.75f; wy1 = 0.25f; }
    else       { y0 = hy - 1; y1 = hy;     wy0 = 0.25f; wy1 = 0.75f; }
    int x0, x1; float wx0, wx1;
    if (x & 1) { x0 = hx;     x1 = hx + 1; wx0 = 0.75f; wx1 = 0.25f; }
    else       { x0 = hx - 1; x1 = hx;     wx0 = 0.25f; wx1 = 0.75f; }
    if (sy) { y0 = hy; y1 = hy; }
    if (sx) { x0 = hx; x1 = hx; }
    float c0, c1;
    if (sy) {
        c0 = P[y0 * CW2 + x0];
        c1 = P[y0 * CW2 + x1];
    } else {
        c0 = __fadd_rn(__fmul_rn(P[y0 * CW2 + x0], wy0), __fmul_rn(P[y1 * CW2 + x0], wy1));
        c1 = __fadd_rn(__fmul_rn(P[y0 * CW2 + x1], wy0), __fmul_rn(P[y1 * CW2 + x1], wy1));
    }
    if (sx) return c0;
    return __fadd_rn(__fmul_rn(c0, wx0), __fmul_rn(c1, wx1));
}

__global__ void k_recon(float* __restrict__ out)
{
    int t = blockIdx.x * blockDim.x + threadIdx.x;
    if (t >= PLANE_Y) return;
    int x = t & 511;
    int y = (t >> 9) & 511;
    int b = t >> 18;
    float yv = g_rY[t];

    size_t cb = (size_t)b * CH2 * CW2;
    float u = __fadd_rn(up2(g_rU + cb, y, x), -128.0f);
    float v = __fadd_rn(up2(g_rV + cb, y, x), -128.0f);

    float R  = __fadd_rn(yv, __fmul_rn(v, 1.402f));
    float G  = __fadd_rn(__fadd_rn(yv, __fmul_rn(u, -0.344136f)), __fmul_rn(v, -0.714136f));
    float Bc = __fadd_rn(yv, __fmul_rn(u, 1.772f));
    R  = __fdiv_rn(fminf(fmaxf(R,  0.f), 255.f), 255.0f);
    G  = __fdiv_rn(fminf(fmaxf(G,  0.f), 255.f), 255.0f);
    Bc = __fdiv_rn(fminf(fmaxf(Bc, 0.f), 255.f), 255.0f);

    size_t ob = (size_t)b * 3 * IH * IW + (size_t)y * IW + x;
    out[ob]               = R;
    out[ob + IH * IW]     = G;
    out[ob + 2 * IH * IW] = Bc;
}

extern "C" void kernel_launch(void* const* d_in, const int* in_sizes, int n_in,
                              void* d_out, int out_size)
{
    const float* img = (const float*)d_in[0];
    const float* lq  = (const float*)d_in[1];
    const float* cq  = (const float*)d_in[2];
    float* out = (float*)d_out;

    // output layout: rgb | qY | qU | qV (reference return order, flattened)
    float* qY = out + 12582912;
    float* qU = out + 16777216;
    float* qV = out + 17825792;

    k_csc<<<(PLANE_C + 255) / 256, 256>>>(img);
    k_fwd<<<NT_ALL / 32, 256>>>(lq, cq, qY, qU, qV);
    k_inv<<<NT_ALL / 32, 256>>>(lq, cq, qY, qU, qV);
    k_recon<<<(PLANE_Y + 255) / 256, 256>>>(out);
}

// round 9
// speedup vs baseline: 1.1893x; 1.1176x over previous
#include <cuda_runtime.h>
#include <math.h>

#define NBATCH 16
#define IH 512
#define IW 512
#define CH2 256
#define CW2 256
#define PLANE_Y (NBATCH * IH * IW)
#define PLANE_C (NBATCH * CH2 * CW2)

#define NT_Y (NBATCH * 64 * 64)   // 65536 luma tiles
#define NT_C (NBATCH * 32 * 32)   // 16384 chroma tiles per plane
#define NT_ALL (NT_Y + 2 * NT_C)  // 98304

// ---- scratch planes (static device globals; no runtime allocation) ----
__device__ float g_Y[PLANE_Y];
__device__ float g_U[PLANE_C];
__device__ float g_V[PLANE_C];
__device__ float g_rY[PLANE_Y];
__device__ float g_rU[PLANE_C];
__device__ float g_rV[PLANE_C];

// ---- compile-time DCT tables, replicating numpy fp64->fp32 exactly ----
__host__ __device__ constexpr double kCosV(int k) {
    return (k == 0) ? 1.0
         : (k == 1) ? 0.98078528040323044913
         : (k == 2) ? 0.92387953251128675613
         : (k == 3) ? 0.83146961230254523708
         : (k == 4) ? 0.70710678118654752440
         : (k == 5) ? 0.55557023301960222474
         : (k == 6) ? 0.38268343236508977173
         : (k == 7) ? 0.19509032201612826785
         : 0.0;
}

__host__ __device__ constexpr double cos16(int k) {
    k &= 31;
    if (k > 16) k = 32 - k;
    return (k <= 8) ? kCosV(k) : -kCosV(16 - k);
}
__host__ __device__ constexpr float Dc(int i, int j) {
    return (float)((j == 0) ? 0.35355339059327376220
                            : 0.5 * cos16((2 * i + 1) * j));
}

struct WTab { float w[64][64]; };
__host__ __device__ constexpr WTab makeW() {
    WTab t{};
    for (int p = 0; p < 64; p++)
        for (int f = 0; f < 64; f++)
            t.w[p][f] = Dc(p >> 3, f >> 3) * Dc(p & 7, f & 7);  // fp32 product (jnp.kron)
    return t;
}
__device__ constexpr WTab WT = makeW();

// ---- tile geometry helper (unified Y/U/V tile index) ----
struct TileInfo {
    const float* plane;
    float*       rec;
    float*       qbase;
    int          width;
    int          qsel;
    size_t       po;
    int          tp;
};

__device__ __forceinline__ TileInfo tile_info(int tile, float* qY, float* qU, float* qV)
{
    TileInfo ti;
    int tp, nbx, height;
    if (tile < NT_Y) {
        tp = tile;           ti.plane = g_Y; ti.rec = g_rY; ti.qbase = qY;
        ti.width = IW;  height = IH;  ti.qsel = 0;
    } else if (tile < NT_Y + NT_C) {
        tp = tile - NT_Y;    ti.plane = g_U; ti.rec = g_rU; ti.qbase = qU;
        ti.width = CW2; height = CH2; ti.qsel = 1;
    } else {
        tp = tile - NT_Y - NT_C; ti.plane = g_V; ti.rec = g_rV; ti.qbase = qV;
        ti.width = CW2; height = CH2; ti.qsel = 1;
    }
    nbx = ti.width >> 3;
    int nbpi = (height >> 3) * nbx;
    int b  = tp / nbpi, r = tp - b * nbpi;
    int by = r / nbx,  bx = r - by * nbx;
    ti.po = ((size_t)b * height + by * 8) * ti.width + bx * 8;
    ti.tp = tp;
    return ti;
}

// ---- RGB -> YUV (+128 chroma) and 2x2 chroma mean ----
// Reference semantics (validated bit-exact): no-FMA dot, pairwise mean.
__global__ void k_csc(const float* __restrict__ img)
{
    int t = blockIdx.x * blockDim.x + threadIdx.x;
    if (t >= PLANE_C) return;
    int cx = t & 255;
    int cy = (t >> 8) & 255;
    int b  = t >> 16;
    const float* Rp = img + (size_t)b * 3 * IH * IW;
    const float* Gp = Rp + IH * IW;
    const float* Bp = Rp + 2 * IH * IW;
    int o0 = (cy * 2) * IW + cx * 2;
    int o1 = o0 + IW;
    float2 r0 = *(const float2*)(Rp + o0), r1 = *(const float2*)(Rp + o1);
    float2 g0 = *(const float2*)(Gp + o0), g1 = *(const float2*)(Gp + o1);
    float2 b0 = *(const float2*)(Bp + o0), b1 = *(const float2*)(Bp + o1);

    float rr[4] = {r0.x, r0.y, r1.x, r1.y};
    float gg[4] = {g0.x, g0.y, g1.x, g1.y};
    float bb[4] = {b0.x, b0.y, b1.x, b1.y};
    float y[4], u[4], v[4];
#pragma unroll
    for (int i = 0; i < 4; i++) {
        float r  = __fmul_rn(rr[i], 255.0f);
        float g  = __fmul_rn(gg[i], 255.0f);
        float bl = __fmul_rn(bb[i], 255.0f);
        y[i] = __fadd_rn(__fadd_rn(__fmul_rn(r, 0.299f),
                                   __fmul_rn(g, 0.587f)),
                         __fmul_rn(bl, 0.114f));
        u[i] = __fadd_rn(__fadd_rn(__fadd_rn(__fmul_rn(r, -0.168736f),
                                             __fmul_rn(g, -0.331264f)),
                                   __fmul_rn(bl, 0.5f)), 128.0f);
        v[i] = __fadd_rn(__fadd_rn(__fadd_rn(__fmul_rn(r, 0.5f),
                                             __fmul_rn(g, -0.418688f)),
                                   __fmul_rn(bl, -0.081312f)), 128.0f);
    }
    float* yb = g_Y + (size_t)b * IH * IW;
    *(float2*)(yb + o0) = make_float2(y[0], y[1]);
    *(float2*)(yb + o1) = make_float2(y[2], y[3]);
    g_U[t] = __fmul_rn(__fadd_rn(__fadd_rn(u[0], u[1]), __fadd_rn(u[2], u[3])), 0.25f);
    g_V[t] = __fmul_rn(__fadd_rn(__fadd_rn(v[0], v[1]), __fadd_rn(v[2], v[3])), 0.25f);
}

// ---- forward accumulation for f-group FG: all weights are literal immediates ----
template<int FG>
__device__ __forceinline__ void fwd_accum(const float* __restrict__ xs, float a[8])
{
#pragma unroll
    for (int pp = 0; pp < 64; pp++) {
        float xv = xs[pp];
#pragma unroll
        for (int u = 0; u < 8; u++)
            a[u] = fmaf(xv, WT.w[pp][FG * 8 + u], a[u]);
    }
}

// ---- fused forward: all planes, 8 threads/tile via warp-specialized f-groups ----
__global__ void __launch_bounds__(256) k_fwd(const float* __restrict__ lq,
                                             const float* __restrict__ cq,
                                             float* __restrict__ qY,
                                             float* __restrict__ qU,
                                             float* __restrict__ qV)
{
    __shared__ float xs[32 * 65];
    __shared__ float Qs[2][64];

    int t = threadIdx.x;
    if (t < 64)              Qs[0][t]      = lq[t];
    else if (t < 128)        Qs[1][t - 64] = cq[t - 64];

    {
        int tileL = t & 31;
        int row   = t >> 5;
        int tile  = blockIdx.x * 32 + tileL;
        TileInfo ti = tile_info(tile, qY, qU, qV);
        const float* p = ti.plane + ti.po + (size_t)row * ti.width;
        float4 v0 = *(const float4*)(p);
        float4 v1 = *(const float4*)(p + 4);
        float* xr = xs + tileL * 65 + row * 8;
        xr[0] = v0.x - 128.f; xr[1] = v0.y - 128.f; xr[2] = v0.z - 128.f; xr[3] = v0.w - 128.f;
        xr[4] = v1.x - 128.f; xr[5] = v1.y - 128.f; xr[6] = v1.z - 128.f; xr[7] = v1.w - 128.f;
    }
    __syncthreads();

    int wid  = t >> 5;
    int lane = t & 31;
    int tile = blockIdx.x * 32 + lane;
    TileInfo ti = tile_info(tile, qY, qU, qV);

    float a[8] = {0.f, 0.f, 0.f, 0.f, 0.f, 0.f, 0.f, 0.f};
    const float* xl = xs + lane * 65;
    switch (wid) {
        case 0: fwd_accum<0>(xl, a); break;
        case 1: fwd_accum<1>(xl, a); break;
        case 2: fwd_accum<2>(xl, a); break;
        case 3: fwd_accum<3>(xl, a); break;
        case 4: fwd_accum<4>(xl, a); break;
        case 5: fwd_accum<5>(xl, a); break;
        case 6: fwd_accum<6>(xl, a); break;
        case 7: fwd_accum<7>(xl, a); break;
    }

    float q[8];
    const float* Qt = Qs[ti.qsel] + wid * 8;
#pragma unroll
    for (int u = 0; u < 8; u++)
        q[u] = rintf(__fdiv_rn(a[u], Qt[u]));

    float* qo = ti.qbase + (size_t)ti.tp * 64 + wid * 8;
    *(float4*)(qo)     = make_float4(q[0], q[1], q[2], q[3]);
    *(float4*)(qo + 4) = make_float4(q[4], q[5], q[6], q[7]);
}

// ---- inverse rows for output row R: D constants fold to literal immediates ----
template<int R>
__device__ __forceinline__ void inv_rows(const float* __restrict__ Cs, float o[8])
{
    float T[8];
#pragma unroll
    for (int j2 = 0; j2 < 8; j2++) {
        float s = 0.f;
#pragma unroll
        for (int j1 = 0; j1 < 8; j1++)
            s = fmaf(Dc(R, j1), Cs[j1 * 8 + j2], s);
        T[j2] = s;
    }
#pragma unroll
    for (int c = 0; c < 8; c++) {
        float s = 0.f;
#pragma unroll
        for (int j2 = 0; j2 < 8; j2++)
            s = fmaf(T[j2], Dc(c, j2), s);
        o[c] = s + 128.f;
    }
}

// ---- fused inverse: all planes, 8 threads/tile ----
__global__ void __launch_bounds__(256) k_inv(const float* __restrict__ lq,
                                             const float* __restrict__ cq,
                                             float* __restrict__ qY,
                                             float* __restrict__ qU,
                                             float* __restrict__ qV)
{
    __shared__ float Cs[32 * 65];
    __shared__ float Qs[2][64];

    int t = threadIdx.x;
    if (t < 64)              Qs[0][t]      = lq[t];
    else if (t < 128)        Qs[1][t - 64] = cq[t - 64];
    __syncthreads();

    int tileL = t & 31;
    int row   = t >> 5;
    int tile  = blockIdx.x * 32 + tileL;
    TileInfo ti = tile_info(tile, qY, qU, qV);

    {
        const float* qi = ti.qbase + (size_t)ti.tp * 64 + row * 8;
        float4 v0 = *(const float4*)(qi);
        float4 v1 = *(const float4*)(qi + 4);
        const float* Qt = Qs[ti.qsel] + row * 8;
        float* cr = Cs + tileL * 65 + row * 8;
        cr[0] = __fmul_rn(v0.x, Qt[0]); cr[1] = __fmul_rn(v0.y, Qt[1]);
        cr[2] = __fmul_rn(v0.z, Qt[2]); cr[3] = __fmul_rn(v0.w, Qt[3]);
        cr[4] = __fmul_rn(v1.x, Qt[4]); cr[5] = __fmul_rn(v1.y, Qt[5]);
        cr[6] = __fmul_rn(v1.z, Qt[6]); cr[7] = __fmul_rn(v1.w, Qt[7]);
    }
    __syncthreads();

    float o[8];
    const float* cl = Cs + tileL * 65;
    switch (row) {
        case 0: inv_rows<0>(cl, o); break;
        case 1: inv_rows<1>(cl, o); break;
        case 2: inv_rows<2>(cl, o); break;
        case 3: inv_rows<3>(cl, o); break;
        case 4: inv_rows<4>(cl, o); break;
        case 5: inv_rows<5>(cl, o); break;
        case 6: inv_rows<6>(cl, o); break;
        case 7: inv_rows<7>(cl, o); break;
    }

    float* rp = ti.rec + ti.po + (size_t)row * ti.width;
    *(float4*)(rp)     = make_float4(o[0], o[1], o[2], o[3]);
    *(float4*)(rp + 4) = make_float4(o[4], o[5], o[6], o[7]);
}

// ---- quad recon: one thread per 2x2 output quad (= one chroma site) ----
// Bit-identical to the per-pixel up2: vertical lerp first, then horizontal,
// same __fadd_rn/__fmul_rn expressions and same edge selections.
__global__ void __launch_bounds__(256) k_recon(float* __restrict__ out)
{
    int t = blockIdx.x * blockDim.x + threadIdx.x;
    if (t >= PLANE_C) return;
    int cx = t & 255;
    int cy = (t >> 8) & 255;
    int b  = t >> 16;

    size_t cb = (size_t)b * CH2 * CW2;
    const float* Up = g_rU + cb;
    const float* Vp = g_rV + cb;

    int cxm = max(cx - 1, 0), cxp = min(cx + 1, 255);
    int cym = max(cy - 1, 0), cyp = min(cy + 1, 255);
    bool y_top = (cy == 0), y_bot = (cy == 255);
    bool x_lft = (cx == 0), x_rgt = (cx == 255);

    int cols[3] = {cxm, cx, cxp};
    float ue[3], uo[3], ve[3], vo[3];
#pragma unroll
    for (int c = 0; c < 3; c++) {
        int col = cols[c];
        float ua = Up[cym * CW2 + col], um = Up[cy * CW2 + col], up = Up[cyp * CW2 + col];
        float va = Vp[cym * CW2 + col], vm = Vp[cy * CW2 + col], vp = Vp[cyp * CW2 + col];
        // even output row (y = 2cy): weights 0.25 on row above, 0.75 on row; edge y==0 -> direct
        ue[c] = y_top ? um : __fadd_rn(__fmul_rn(ua, 0.25f), __fmul_rn(um, 0.75f));
        ve[c] = y_top ? vm : __fadd_rn(__fmul_rn(va, 0.25f), __fmul_rn(vm, 0.75f));
        // odd output row (y = 2cy+1): 0.75 on row, 0.25 on row below; edge y==511 -> direct
        uo[c] = y_bot ? um : __fadd_rn(__fmul_rn(um, 0.75f), __fmul_rn(up, 0.25f));
        vo[c] = y_bot ? vm : __fadd_rn(__fmul_rn(vm, 0.75f), __fmul_rn(vp, 0.25f));
    }

    // horizontal: even x (2cx): 0.25*col(cx-1) + 0.75*col(cx); edge x==0 -> direct
    //             odd  x (2cx+1): 0.75*col(cx) + 0.25*col(cx+1); edge x==511 -> direct
    float u00 = x_lft ? ue[1] : __fadd_rn(__fmul_rn(ue[0], 0.25f), __fmul_rn(ue[1], 0.75f));
    float u01 = x_rgt ? ue[1] : __fadd_rn(__fmul_rn(ue[1], 0.75f), __fmul_rn(ue[2], 0.25f));
    float u10 = x_lft ? uo[1] : __fadd_rn(__fmul_rn(uo[0], 0.25f), __fmul_rn(uo[1], 0.75f));
    float u11 = x_rgt ? uo[1] : __fadd_rn(__fmul_rn(uo[1], 0.75f), __fmul_rn(uo[2], 0.25f));
    float v00 = x_lft ? ve[1] : __fadd_rn(__fmul_rn(ve[0], 0.25f), __fmul_rn(ve[1], 0.75f));
    float v01 = x_rgt ? ve[1] : __fadd_rn(__fmul_rn(ve[1], 0.75f), __fmul_rn(ve[2], 0.25f));
    float v10 = x_lft ? vo[1] : __fadd_rn(__fmul_rn(vo[0], 0.25f), __fmul_rn(vo[1], 0.75f));
    float v11 = x_rgt ? vo[1] : __fadd_rn(__fmul_rn(vo[1], 0.75f), __fmul_rn(vo[2], 0.25f));

    // luma quad
    size_t yo0 = ((size_t)b * IH + cy * 2) * IW + cx * 2;
    size_t yo1 = yo0 + IW;
    float2 yr0 = *(const float2*)(g_rY + yo0);
    float2 yr1 = *(const float2*)(g_rY + yo1);

    float yq[4] = {yr0.x, yr0.y, yr1.x, yr1.y};
    float uq[4] = {u00, u01, u10, u11};
    float vq[4] = {v00, v01, v10, v11};
    float R[4], G[4], B[4];
#pragma unroll
    for (int i = 0; i < 4; i++) {
        float uu = __fadd_rn(uq[i], -128.0f);
        float vv = __fadd_rn(vq[i], -128.0f);
        float yv = yq[i];
        float r  = __fadd_rn(yv, __fmul_rn(vv, 1.402f));
        float g  = __fadd_rn(__fadd_rn(yv, __fmul_rn(uu, -0.344136f)), __fmul_rn(vv, -0.714136f));
        float bl = __fadd_rn(yv, __fmul_rn(uu, 1.772f));
        R[i] = __fdiv_rn(fminf(fmaxf(r,  0.f), 255.f), 255.0f);
        G[i] = __fdiv_rn(fminf(fmaxf(g,  0.f), 255.f), 255.0f);
        B[i] = __fdiv_rn(fminf(fmaxf(bl, 0.f), 255.f), 255.0f);
    }

    size_t ob0 = (size_t)b * 3 * IH * IW + ((size_t)cy * 2) * IW + cx * 2;
    size_t ob1 = ob0 + IW;
    *(float2*)(out + ob0)                 = make_float2(R[0], R[1]);
    *(float2*)(out + ob1)                 = make_float2(R[2], R[3]);
    *(float2*)(out + ob0 + IH * IW)       = make_float2(G[0], G[1]);
    *(float2*)(out + ob1 + IH * IW)       = make_float2(G[2], G[3]);
    *(float2*)(out + ob0 + 2 * IH * IW)   = make_float2(B[0], B[1]);
    *(float2*)(out + ob1 + 2 * IH * IW)   = make_float2(B[2], B[3]);
}

extern "C" void kernel_launch(void* const* d_in, const int* in_sizes, int n_in,
                              void* d_out, int out_size)
{
    const float* img = (const float*)d_in[0];
    const float* lq  = (const float*)d_in[1];
    const float* cq  = (const float*)d_in[2];
    float* out = (float*)d_out;

    // output layout: rgb | qY | qU | qV (reference return order, flattened)
    float* qY = out + 12582912;
    float* qU = out + 16777216;
    float* qV = out + 17825792;

    k_csc<<<(PLANE_C + 255) / 256, 256>>>(img);
    k_fwd<<<NT_ALL / 32, 256>>>(lq, cq, qY, qU, qV);
    k_inv<<<NT_ALL / 32, 256>>>(lq, cq, qY, qU, qV);
    k_recon<<<(PLANE_C + 255) / 256, 256>>>(out);
}